// round 6
// baseline (speedup 1.0000x reference)
#include <cuda_runtime.h>
#include <math.h>

#define HID  4096
#define NH   32
#define DD   128
#define II   4096
#define EPSF 1e-6f

// ---------------- scratch (no device allocations allowed) ----------------
__device__ float g_qkv[3 * II];
__device__ float g_z[II];
__device__ float g_a[NH];
__device__ float g_b[NH];
__device__ float g_c[II];                 // cn (pre z-gate)
__device__ float g_pkv[256 * DD];         // kv partials  [(h*8+ck)*128+e]
__device__ float g_pco[256 * DD];         // core partials
__device__ unsigned g_hd0[NH];            // monotonic per-head barrier counters
__device__ unsigned g_hd1[NH];

__device__ __forceinline__ float siluf(float y) { return y / (1.f + expf(-y)); }

// ---------------- A1: GEMV (W_qkv | W_a | W_b), 12352 rows ----------------
__global__ void __launch_bounds__(256) gemv_qkvab(
    const float* __restrict__ hs,
    const float* __restrict__ Wqkv,
    const float* __restrict__ Wa,
    const float* __restrict__ Wb)
{
    __shared__ float4 sh[HID / 4];
    const int tid = threadIdx.x;
    const float4* h4 = (const float4*)hs;
    #pragma unroll
    for (int i = tid; i < HID / 4; i += 256) sh[i] = h4[i];
    __syncthreads();

    const int warp = tid >> 5;
    const int lane = tid & 31;
    const int row  = blockIdx.x * 8 + warp;

    const float* Wrow;
    float* outp;
    if (row < 3 * II)           { Wrow = Wqkv + (size_t)row * HID;              outp = &g_qkv[row]; }
    else if (row < 3 * II + NH) { Wrow = Wa + (size_t)(row - 3 * II) * HID;     outp = &g_a[row - 3 * II]; }
    else                        { Wrow = Wb + (size_t)(row - 3 * II - NH) * HID; outp = &g_b[row - 3 * II - NH]; }

    const float4* W4 = (const float4*)Wrow;
    float a0 = 0.f, a1 = 0.f, a2 = 0.f, a3 = 0.f;
    #pragma unroll
    for (int j = lane; j < HID / 4; j += 128) {
        float4 w0 = W4[j      ], x0 = sh[j      ];
        float4 w1 = W4[j +  32], x1 = sh[j +  32];
        float4 w2 = W4[j +  64], x2 = sh[j +  64];
        float4 w3 = W4[j +  96], x3 = sh[j +  96];
        a0 += w0.x*x0.x + w0.y*x0.y + w0.z*x0.z + w0.w*x0.w;
        a1 += w1.x*x1.x + w1.y*x1.y + w1.z*x1.z + w1.w*x1.w;
        a2 += w2.x*x2.x + w2.y*x2.y + w2.z*x2.z + w2.w*x2.w;
        a3 += w3.x*x3.x + w3.y*x3.y + w3.z*x3.z + w3.w*x3.w;
    }
    float acc = (a0 + a1) + (a2 + a3);
    #pragma unroll
    for (int o = 16; o; o >>= 1) acc += __shfl_xor_sync(0xffffffffu, acc, o);
    if (lane == 0) *outp = acc;
}

// ---------------- A2: GEMV W_z, split: 2 warps per row, grid 1024 ----------------
__global__ void __launch_bounds__(256) gemv_z(
    const float* __restrict__ hs,
    const float* __restrict__ Wz)
{
    __shared__ float4 sh[HID / 4];
    __shared__ float s_red[8];
    const int tid = threadIdx.x;
    const float4* h4 = (const float4*)hs;
    #pragma unroll
    for (int i = tid; i < HID / 4; i += 256) sh[i] = h4[i];
    __syncthreads();

    const int warp = tid >> 5;
    const int lane = tid & 31;
    const int row  = blockIdx.x * 4 + (warp >> 1);
    const int half = warp & 1;

    const float4* W4 = (const float4*)(Wz + (size_t)row * HID) + half * 512;
    const float4* X4 = sh + half * 512;
    float a0 = 0.f, a1 = 0.f, a2 = 0.f, a3 = 0.f;
    #pragma unroll
    for (int t = 0; t < 4; t++) {
        const int j = lane + t * 128;
        float4 w0 = W4[j      ], x0 = X4[j      ];
        float4 w1 = W4[j +  32], x1 = X4[j +  32];
        float4 w2 = W4[j +  64], x2 = X4[j +  64];
        float4 w3 = W4[j +  96], x3 = X4[j +  96];
        a0 += w0.x*x0.x + w0.y*x0.y + w0.z*x0.z + w0.w*x0.w;
        a1 += w1.x*x1.x + w1.y*x1.y + w1.z*x1.z + w1.w*x1.w;
        a2 += w2.x*x2.x + w2.y*x2.y + w2.z*x2.z + w2.w*x2.w;
        a3 += w3.x*x3.x + w3.y*x3.y + w3.z*x3.z + w3.w*x3.w;
    }
    float acc = (a0 + a1) + (a2 + a3);
    #pragma unroll
    for (int o = 16; o; o >>= 1) acc += __shfl_xor_sync(0xffffffffu, acc, o);
    if (lane == 0) s_red[warp] = acc;
    __syncthreads();
    if (tid < 4) g_z[blockIdx.x * 4 + tid] = s_red[2 * tid] + s_red[2 * tid + 1];
}

// ---------------- B: conv + delta-rule state update, 256 blocks ----------------
__global__ void __launch_bounds__(128) delta_state(
    const float* __restrict__ rnn_state,
    const float* __restrict__ conv_state,
    const float* __restrict__ conv_w,
    const float* __restrict__ conv_b,
    const float* __restrict__ A_log,
    const float* __restrict__ dt_bias,
    const float* __restrict__ norm_w,
    float* __restrict__ out_state,
    float* __restrict__ out_conv)
{
    const int h  = blockIdx.x >> 3;
    const int ck = blockIdx.x & 7;
    const int e  = threadIdx.x;       // 0..127
    const int d0 = ck * 16;

    __shared__ float s_qkv[384];
    __shared__ float s_kn[DD];
    __shared__ float s_qn[DD];
    __shared__ float s_core[DD];
    __shared__ float s_scal[4];

    #pragma unroll
    for (int part = 0; part < 3; part++) {
        const int c = part * II + h * DD + e;
        const float c0 = conv_state[c*3+0], c1 = conv_state[c*3+1], c2 = conv_state[c*3+2];
        const float xn = g_qkv[c];
        const float y = c0*conv_w[c*4+0] + c1*conv_w[c*4+1] + c2*conv_w[c*4+2]
                      + xn*conv_w[c*4+3] + conv_b[c];
        s_qkv[part * DD + e] = siluf(y);
        if (ck == 0) {
            out_conv[c*3+0] = c1; out_conv[c*3+1] = c2; out_conv[c*3+2] = xn;
        }
    }
    __syncthreads();

    if (e < 64) {
        const float* base = (e < 32) ? s_qkv : (s_qkv + DD);
        const int l = e & 31;
        float v0 = base[l], v1 = base[l+32], v2 = base[l+64], v3 = base[l+96];
        float x = v0*v0 + v1*v1 + v2*v2 + v3*v3;
        #pragma unroll
        for (int o = 16; o; o >>= 1) x += __shfl_xor_sync(0xffffffffu, x, o);
        if (l == 0) s_scal[e >> 5] = x;
    }
    __syncthreads();
    s_qn[e] = s_qkv[e]       / fmaxf(sqrtf(s_scal[0]), EPSF) * 0.08838834764831845f;
    s_kn[e] = s_qkv[DD + e]  / fmaxf(sqrtf(s_scal[1]), EPSF);
    __syncthreads();

    const float beta = 1.f / (1.f + expf(-g_b[h]));
    const float xg   = g_a[h] + dt_bias[h];
    const float sp   = (xg > 20.f) ? xg : log1pf(expf(xg));
    const float eg   = expf(-expf(A_log[h]) * sp);

    const float* st  = rnn_state + (size_t)h * DD * DD;
    float*       ost = out_state + (size_t)h * DD * DD;

    float kvp = 0.f;
    #pragma unroll
    for (int i = 0; i < 16; i++) kvp += st[(d0 + i) * DD + e] * s_kn[d0 + i];
    g_pkv[blockIdx.x * DD + e] = kvp;
    __threadfence();
    __syncthreads();
    if (e == 0) {
        unsigned old  = atomicAdd(&g_hd0[h], 1u);
        unsigned need = (old / 8u + 1u) * 8u;
        while (*((volatile unsigned*)&g_hd0[h]) < need) { }
        __threadfence();
    }
    __syncthreads();

    float kv = 0.f;
    #pragma unroll
    for (int c = 0; c < 8; c++) kv += g_pkv[(h * 8 + c) * DD + e];
    const float delta = (s_qkv[2 * DD + e] - kv * eg) * beta;

    float corep = 0.f;
    #pragma unroll
    for (int i = 0; i < 16; i++) {
        const float ns = st[(d0 + i) * DD + e] * eg + s_kn[d0 + i] * delta;
        ost[(d0 + i) * DD + e] = ns;
        corep += ns * s_qn[d0 + i];
    }
    g_pco[blockIdx.x * DD + e] = corep;
    __threadfence();
    __syncthreads();
    if (e == 0) {
        unsigned old  = atomicAdd(&g_hd1[h], 1u);
        if (ck == 0) {
            unsigned need = (old / 8u + 1u) * 8u;
            while (*((volatile unsigned*)&g_hd1[h]) < need) { }
            __threadfence();
        }
    }
    if (ck != 0) return;
    __syncthreads();

    float core = 0.f;
    #pragma unroll
    for (int c = 0; c < 8; c++) core += g_pco[(h * 8 + c) * DD + e];
    s_core[e] = core;
    __syncthreads();
    if (e < 32) {
        float c0 = s_core[e], c1 = s_core[e+32], c2 = s_core[e+64], c3 = s_core[e+96];
        float x = c0*c0 + c1*c1 + c2*c2 + c3*c3;
        #pragma unroll
        for (int o = 16; o; o >>= 1) x += __shfl_xor_sync(0xffffffffu, x, o);
        if (e == 0) s_scal[2] = x;
    }
    __syncthreads();
    const float var = s_scal[2] * (1.f / DD);
    g_c[h * DD + e] = norm_w[e] * s_core[e] * rsqrtf(var + EPSF);
}

// ---------------- C: out = W_out @ (cn * silu(z)), split: 2 warps/row ----------------
__global__ void __launch_bounds__(256) gemv_out(
    const float* __restrict__ Wout,
    float* __restrict__ out)
{
    __shared__ float4 sh[II / 4];
    __shared__ float s_red[8];
    const int tid = threadIdx.x;
    const float4* c4 = (const float4*)g_c;
    const float4* z4 = (const float4*)g_z;
    #pragma unroll
    for (int i = tid; i < II / 4; i += 256) {
        float4 c = c4[i], z = z4[i];
        sh[i] = make_float4(c.x * siluf(z.x), c.y * siluf(z.y),
                            c.z * siluf(z.z), c.w * siluf(z.w));
    }
    __syncthreads();

    const int warp = tid >> 5;
    const int lane = tid & 31;
    const int row  = blockIdx.x * 4 + (warp >> 1);
    const int half = warp & 1;

    const float4* W4 = (const float4*)(Wout + (size_t)row * II) + half * 512;
    const float4* X4 = sh + half * 512;
    float a0 = 0.f, a1 = 0.f, a2 = 0.f, a3 = 0.f;
    #pragma unroll
    for (int t = 0; t < 4; t++) {
        const int j = lane + t * 128;
        float4 w0 = W4[j      ], x0 = X4[j      ];
        float4 w1 = W4[j +  32], x1 = X4[j +  32];
        float4 w2 = W4[j +  64], x2 = X4[j +  64];
        float4 w3 = W4[j +  96], x3 = X4[j +  96];
        a0 += w0.x*x0.x + w0.y*x0.y + w0.z*x0.z + w0.w*x0.w;
        a1 += w1.x*x1.x + w1.y*x1.y + w1.z*x1.z + w1.w*x1.w;
        a2 += w2.x*x2.x + w2.y*x2.y + w2.z*x2.z + w2.w*x2.w;
        a3 += w3.x*x3.x + w3.y*x3.y + w3.z*x3.z + w3.w*x3.w;
    }
    float acc = (a0 + a1) + (a2 + a3);
    #pragma unroll
    for (int o = 16; o; o >>= 1) acc += __shfl_xor_sync(0xffffffffu, acc, o);
    if (lane == 0) s_red[warp] = acc;
    __syncthreads();
    if (tid < 4) out[blockIdx.x * 4 + tid] = s_red[2 * tid] + s_red[2 * tid + 1];
}

// ---------------- host: capture-forked two-stream launch ----------------
static cudaStream_t g_s2;
static cudaEvent_t  g_ev1, g_ev2;
static struct HostInit {
    HostInit() {
        cudaStreamCreateWithFlags(&g_s2, cudaStreamNonBlocking);
        cudaEventCreateWithFlags(&g_ev1, cudaEventDisableTiming);
        cudaEventCreateWithFlags(&g_ev2, cudaEventDisableTiming);
    }
} g_hostInit;

extern "C" void kernel_launch(void* const* d_in, const int* in_sizes, int n_in,
                              void* d_out, int out_size)
{
    const float* hs   = (const float*)d_in[0];
    const float* rnn  = (const float*)d_in[1];
    const float* cs   = (const float*)d_in[2];
    const float* Wqkv = (const float*)d_in[3];
    const float* Wz   = (const float*)d_in[4];
    const float* Wa   = (const float*)d_in[5];
    const float* Wb   = (const float*)d_in[6];
    const float* cw   = (const float*)d_in[7];
    const float* cb   = (const float*)d_in[8];
    const float* Alog = (const float*)d_in[9];
    const float* dtb  = (const float*)d_in[10];
    const float* nw   = (const float*)d_in[11];
    const float* Wout = (const float*)d_in[12];
    float* out = (float*)d_out;

    // A1: qkv + a + b rows (12352 rows)
    gemv_qkvab<<<(3 * II + 2 * NH) / 8, 256>>>(hs, Wqkv, Wa, Wb);

    // fork: A2 (z GEMV) runs concurrently with B on stream s2
    cudaEventRecord(g_ev1, 0);
    cudaStreamWaitEvent(g_s2, g_ev1, 0);
    gemv_z<<<HID / 4, 256, 0, g_s2>>>(hs, Wz);

    // B on main stream (overlaps A2)
    delta_state<<<NH * 8, DD>>>(rnn, cs, cw, cb, Alog, dtb, nw,
                                out + II, out + II + (size_t)NH * DD * DD);

    // join, then C
    cudaEventRecord(g_ev2, g_s2);
    cudaStreamWaitEvent(0, g_ev2, 0);
    gemv_out<<<HID / 4, 256>>>(Wout, out);
}

// round 7
// speedup vs baseline: 1.2410x; 1.2410x over previous
#include <cuda_runtime.h>
#include <math.h>

#define HID  4096
#define NH   32
#define DD   128
#define II   4096
#define EPSF 1e-6f

// ---------------- scratch (no device allocations allowed) ----------------
__device__ float g_qkv[3 * II];
__device__ float g_z[II];                 // silu(z), pre-gated
__device__ float g_a[NH];
__device__ float g_b[NH];
__device__ float g_c[II];                 // cn (pre z-gate)
__device__ float g_pkv[256 * DD];         // kv partials  [(h*8+ck)*128+e]
__device__ float g_pco[256 * DD];         // core partials
__device__ unsigned g_hd0[NH];            // monotonic per-head barrier counters
__device__ unsigned g_hd1[NH];

__device__ __forceinline__ float siluf(float y) { return y / (1.f + expf(-y)); }

// ---------------- A1: GEMV (W_qkv | W_a | W_b), 12352 rows ----------------
__global__ void __launch_bounds__(256) gemv_qkvab(
    const float* __restrict__ hs,
    const float* __restrict__ Wqkv,
    const float* __restrict__ Wa,
    const float* __restrict__ Wb)
{
    __shared__ float4 sh[HID / 4];
    const int tid = threadIdx.x;
    const float4* h4 = (const float4*)hs;
    #pragma unroll
    for (int i = tid; i < HID / 4; i += 256) sh[i] = h4[i];
    __syncthreads();

    const int warp = tid >> 5;
    const int lane = tid & 31;
    const int row  = blockIdx.x * 8 + warp;

    const float* Wrow;
    float* outp;
    if (row < 3 * II)           { Wrow = Wqkv + (size_t)row * HID;              outp = &g_qkv[row]; }
    else if (row < 3 * II + NH) { Wrow = Wa + (size_t)(row - 3 * II) * HID;     outp = &g_a[row - 3 * II]; }
    else                        { Wrow = Wb + (size_t)(row - 3 * II - NH) * HID; outp = &g_b[row - 3 * II - NH]; }

    const float4* W4 = (const float4*)Wrow;
    float a0 = 0.f, a1 = 0.f, a2 = 0.f, a3 = 0.f;
    #pragma unroll
    for (int j = lane; j < HID / 4; j += 128) {
        float4 w0 = W4[j      ], x0 = sh[j      ];
        float4 w1 = W4[j +  32], x1 = sh[j +  32];
        float4 w2 = W4[j +  64], x2 = sh[j +  64];
        float4 w3 = W4[j +  96], x3 = sh[j +  96];
        a0 += w0.x*x0.x + w0.y*x0.y + w0.z*x0.z + w0.w*x0.w;
        a1 += w1.x*x1.x + w1.y*x1.y + w1.z*x1.z + w1.w*x1.w;
        a2 += w2.x*x2.x + w2.y*x2.y + w2.z*x2.z + w2.w*x2.w;
        a3 += w3.x*x3.x + w3.y*x3.y + w3.z*x3.z + w3.w*x3.w;
    }
    float acc = (a0 + a1) + (a2 + a3);
    #pragma unroll
    for (int o = 16; o; o >>= 1) acc += __shfl_xor_sync(0xffffffffu, acc, o);
    if (lane == 0) *outp = acc;
}

// ---------------- A2: GEMV W_z -> stores silu(z) ----------------
__global__ void __launch_bounds__(256) gemv_z(
    const float* __restrict__ hs,
    const float* __restrict__ Wz)
{
    __shared__ float4 sh[HID / 4];
    const int tid = threadIdx.x;
    const float4* h4 = (const float4*)hs;
    #pragma unroll
    for (int i = tid; i < HID / 4; i += 256) sh[i] = h4[i];
    __syncthreads();

    const int warp = tid >> 5;
    const int lane = tid & 31;
    const int row  = blockIdx.x * 8 + warp;

    const float4* W4 = (const float4*)(Wz + (size_t)row * HID);
    float a0 = 0.f, a1 = 0.f, a2 = 0.f, a3 = 0.f;
    #pragma unroll
    for (int j = lane; j < HID / 4; j += 128) {
        float4 w0 = W4[j      ], x0 = sh[j      ];
        float4 w1 = W4[j +  32], x1 = sh[j +  32];
        float4 w2 = W4[j +  64], x2 = sh[j +  64];
        float4 w3 = W4[j +  96], x3 = sh[j +  96];
        a0 += w0.x*x0.x + w0.y*x0.y + w0.z*x0.z + w0.w*x0.w;
        a1 += w1.x*x1.x + w1.y*x1.y + w1.z*x1.z + w1.w*x1.w;
        a2 += w2.x*x2.x + w2.y*x2.y + w2.z*x2.z + w2.w*x2.w;
        a3 += w3.x*x3.x + w3.y*x3.y + w3.z*x3.z + w3.w*x3.w;
    }
    float acc = (a0 + a1) + (a2 + a3);
    #pragma unroll
    for (int o = 16; o; o >>= 1) acc += __shfl_xor_sync(0xffffffffu, acc, o);
    if (lane == 0) g_z[row] = siluf(acc);     // pre-gate: one exp per output elem
}

// ---------------- B: conv + delta-rule state update, 256 blocks ----------------
__global__ void __launch_bounds__(128) delta_state(
    const float* __restrict__ rnn_state,
    const float* __restrict__ conv_state,
    const float* __restrict__ conv_w,
    const float* __restrict__ conv_b,
    const float* __restrict__ A_log,
    const float* __restrict__ dt_bias,
    const float* __restrict__ norm_w,
    float* __restrict__ out_state,
    float* __restrict__ out_conv)
{
    const int h  = blockIdx.x >> 3;
    const int ck = blockIdx.x & 7;
    const int e  = threadIdx.x;       // 0..127
    const int d0 = ck * 16;

    __shared__ float s_qkv[384];
    __shared__ float s_kn[DD];
    __shared__ float s_qn[DD];
    __shared__ float s_core[DD];
    __shared__ float s_scal[4];

    #pragma unroll
    for (int part = 0; part < 3; part++) {
        const int c = part * II + h * DD + e;
        const float c0 = conv_state[c*3+0], c1 = conv_state[c*3+1], c2 = conv_state[c*3+2];
        const float xn = g_qkv[c];
        const float y = c0*conv_w[c*4+0] + c1*conv_w[c*4+1] + c2*conv_w[c*4+2]
                      + xn*conv_w[c*4+3] + conv_b[c];
        s_qkv[part * DD + e] = siluf(y);
        if (ck == 0) {
            out_conv[c*3+0] = c1; out_conv[c*3+1] = c2; out_conv[c*3+2] = xn;
        }
    }
    __syncthreads();

    if (e < 64) {
        const float* base = (e < 32) ? s_qkv : (s_qkv + DD);
        const int l = e & 31;
        float v0 = base[l], v1 = base[l+32], v2 = base[l+64], v3 = base[l+96];
        float x = v0*v0 + v1*v1 + v2*v2 + v3*v3;
        #pragma unroll
        for (int o = 16; o; o >>= 1) x += __shfl_xor_sync(0xffffffffu, x, o);
        if (l == 0) s_scal[e >> 5] = x;
    }
    __syncthreads();
    s_qn[e] = s_qkv[e]       / fmaxf(sqrtf(s_scal[0]), EPSF) * 0.08838834764831845f;
    s_kn[e] = s_qkv[DD + e]  / fmaxf(sqrtf(s_scal[1]), EPSF);
    __syncthreads();

    const float beta = 1.f / (1.f + expf(-g_b[h]));
    const float xg   = g_a[h] + dt_bias[h];
    const float sp   = (xg > 20.f) ? xg : log1pf(expf(xg));
    const float eg   = expf(-expf(A_log[h]) * sp);

    const float* st  = rnn_state + (size_t)h * DD * DD;
    float*       ost = out_state + (size_t)h * DD * DD;

    float kvp = 0.f;
    #pragma unroll
    for (int i = 0; i < 16; i++) kvp += st[(d0 + i) * DD + e] * s_kn[d0 + i];
    g_pkv[blockIdx.x * DD + e] = kvp;
    __threadfence();
    __syncthreads();
    if (e == 0) {
        unsigned old  = atomicAdd(&g_hd0[h], 1u);
        unsigned need = (old / 8u + 1u) * 8u;
        while (*((volatile unsigned*)&g_hd0[h]) < need) { }
        __threadfence();
    }
    __syncthreads();

    float kv = 0.f;
    #pragma unroll
    for (int c = 0; c < 8; c++) kv += g_pkv[(h * 8 + c) * DD + e];
    const float delta = (s_qkv[2 * DD + e] - kv * eg) * beta;

    float corep = 0.f;
    #pragma unroll
    for (int i = 0; i < 16; i++) {
        const float ns = st[(d0 + i) * DD + e] * eg + s_kn[d0 + i] * delta;
        ost[(d0 + i) * DD + e] = ns;
        corep += ns * s_qn[d0 + i];
    }
    g_pco[blockIdx.x * DD + e] = corep;
    __threadfence();
    __syncthreads();
    if (e == 0) {
        unsigned old  = atomicAdd(&g_hd1[h], 1u);
        if (ck == 0) {
            unsigned need = (old / 8u + 1u) * 8u;
            while (*((volatile unsigned*)&g_hd1[h]) < need) { }
            __threadfence();
        }
    }
    if (ck != 0) return;
    __syncthreads();

    float core = 0.f;
    #pragma unroll
    for (int c = 0; c < 8; c++) core += g_pco[(h * 8 + c) * DD + e];
    s_core[e] = core;
    __syncthreads();
    if (e < 32) {
        float c0 = s_core[e], c1 = s_core[e+32], c2 = s_core[e+64], c3 = s_core[e+96];
        float x = c0*c0 + c1*c1 + c2*c2 + c3*c3;
        #pragma unroll
        for (int o = 16; o; o >>= 1) x += __shfl_xor_sync(0xffffffffu, x, o);
        if (e == 0) s_scal[2] = x;
    }
    __syncthreads();
    const float var = s_scal[2] * (1.f / DD);
    g_c[h * DD + e] = norm_w[e] * s_core[e] * rsqrtf(var + EPSF);
}

// ---------------- C: out = W_out @ (cn * silu_z), no exp in staging ----------------
__global__ void __launch_bounds__(256) gemv_out(
    const float* __restrict__ Wout,
    float* __restrict__ out)
{
    __shared__ float4 sh[II / 4];
    const int tid = threadIdx.x;
    const float4* c4 = (const float4*)g_c;
    const float4* z4 = (const float4*)g_z;
    #pragma unroll
    for (int i = tid; i < II / 4; i += 256) {
        float4 c = c4[i], z = z4[i];
        sh[i] = make_float4(c.x * z.x, c.y * z.y, c.z * z.z, c.w * z.w);
    }
    __syncthreads();

    const int warp = tid >> 5;
    const int lane = tid & 31;
    const int row  = blockIdx.x * 8 + warp;

    const float4* W4 = (const float4*)(Wout + (size_t)row * II);
    float a0 = 0.f, a1 = 0.f, a2 = 0.f, a3 = 0.f;
    #pragma unroll
    for (int j = lane; j < II / 4; j += 128) {
        float4 w0 = W4[j      ], x0 = sh[j      ];
        float4 w1 = W4[j +  32], x1 = sh[j +  32];
        float4 w2 = W4[j +  64], x2 = sh[j +  64];
        float4 w3 = W4[j +  96], x3 = sh[j +  96];
        a0 += w0.x*x0.x + w0.y*x0.y + w0.z*x0.z + w0.w*x0.w;
        a1 += w1.x*x1.x + w1.y*x1.y + w1.z*x1.z + w1.w*x1.w;
        a2 += w2.x*x2.x + w2.y*x2.y + w2.z*x2.z + w2.w*x2.w;
        a3 += w3.x*x3.x + w3.y*x3.y + w3.z*x3.z + w3.w*x3.w;
    }
    float acc = (a0 + a1) + (a2 + a3);
    #pragma unroll
    for (int o = 16; o; o >>= 1) acc += __shfl_xor_sync(0xffffffffu, acc, o);
    if (lane == 0) out[row] = acc;
}

// ---------------- host: capture-forked two-stream launch ----------------
static cudaStream_t g_s2;
static cudaEvent_t  g_ev1, g_ev2;
static struct HostInit {
    HostInit() {
        cudaStreamCreateWithFlags(&g_s2, cudaStreamNonBlocking);
        cudaEventCreateWithFlags(&g_ev1, cudaEventDisableTiming);
        cudaEventCreateWithFlags(&g_ev2, cudaEventDisableTiming);
    }
} g_hostInit;

extern "C" void kernel_launch(void* const* d_in, const int* in_sizes, int n_in,
                              void* d_out, int out_size)
{
    const float* hs   = (const float*)d_in[0];
    const float* rnn  = (const float*)d_in[1];
    const float* cs   = (const float*)d_in[2];
    const float* Wqkv = (const float*)d_in[3];
    const float* Wz   = (const float*)d_in[4];
    const float* Wa   = (const float*)d_in[5];
    const float* Wb   = (const float*)d_in[6];
    const float* cw   = (const float*)d_in[7];
    const float* cb   = (const float*)d_in[8];
    const float* Alog = (const float*)d_in[9];
    const float* dtb  = (const float*)d_in[10];
    const float* nw   = (const float*)d_in[11];
    const float* Wout = (const float*)d_in[12];
    float* out = (float*)d_out;

    // A1: qkv + a + b rows (12352 rows)
    gemv_qkvab<<<(3 * II + 2 * NH) / 8, 256>>>(hs, Wqkv, Wa, Wb);

    // fork: A2 (z GEMV, stores silu(z)) runs concurrently with B on stream s2
    cudaEventRecord(g_ev1, 0);
    cudaStreamWaitEvent(g_s2, g_ev1, 0);
    gemv_z<<<HID / 8, 256, 0, g_s2>>>(hs, Wz);

    // B on main stream (overlaps A2)
    delta_state<<<NH * 8, DD>>>(rnn, cs, cw, cb, Alog, dtb, nw,
                                out + II, out + II + (size_t)NH * DD * DD);

    // join, then C
    cudaEventRecord(g_ev2, g_s2);
    cudaStreamWaitEvent(0, g_ev2, 0);
    gemv_out<<<HID / 8, 256>>>(Wout, out);
}